// round 3
// baseline (speedup 1.0000x reference)
#include <cuda_runtime.h>
#include <math.h>

// Problem constants (fixed shapes from setup_inputs)
#define NB 2
#define CH 128
#define HH 128
#define WW 128
#define HL 64
#define WL 64
#define PLANE (HH*WW)          // 16384
#define IMG   (CH*PLANE)       // per-batch elems

// Scratch (module-load allocated; no runtime allocs)
__device__ float g_lrup[NB*IMG];
__device__ float g_key [NB*IMG];
__device__ float g_val [NB*IMG];
__device__ float g_qry [NB*IMG];
__device__ float g_s   [NB*2*9*PLANE];   // s[n][o][tap][h][w]
__device__ float g_dyn [NB*2*PLANE];     // dyn[n][o][h][w]

// ---------------------------------------------------------------------------
// Kernel 1: bilinear upsample (align_corners=True) 64x64 -> 128x128
// ---------------------------------------------------------------------------
__global__ void k_lrup(const float* __restrict__ lr) {
    int idx = blockIdx.x * blockDim.x + threadIdx.x;   // (nc, h, w), w fastest
    int w  = idx & (WW-1);
    int h  = (idx >> 7) & (HH-1);
    int nc = idx >> 14;                                 // 0..255

    float ys = (float)(h * (HL-1)) / (float)(HH-1);
    float xs = (float)(w * (WL-1)) / (float)(WW-1);
    int y0 = (int)floorf(ys);
    int x0 = (int)floorf(xs);
    int y1 = min(y0 + 1, HL-1);
    int x1 = min(x0 + 1, WL-1);
    float wy = ys - (float)y0;
    float wx = xs - (float)x0;

    const float* p = lr + nc * (HL*WL);
    float a = p[y0*WL + x0];
    float b = p[y0*WL + x1];
    float c = p[y1*WL + x0];
    float d = p[y1*WL + x1];
    float top = a + (b - a) * wx;
    float bot = c + (d - c) * wx;
    g_lrup[idx] = top + (bot - top) * wy;
}

// ---------------------------------------------------------------------------
// Kernel 2: three depthwise 3x3 convs (key, value from hr_feat; query from lr_up)
// ---------------------------------------------------------------------------
__global__ void k_qkv(const float* __restrict__ hr,
                      const float* __restrict__ wq, const float* __restrict__ bq,
                      const float* __restrict__ wk, const float* __restrict__ bk,
                      const float* __restrict__ wv, const float* __restrict__ bv) {
    int idx = blockIdx.x * blockDim.x + threadIdx.x;   // (n, c, h, w)
    int w = idx & (WW-1);
    int h = (idx >> 7) & (HH-1);
    int c = (idx >> 14) & (CH-1);
    int n = idx >> 21;

    const float* ph = hr     + (n*CH + c) * PLANE;
    const float* pl = g_lrup + (n*CH + c) * PLANE;

    float acck = bk[c];
    float accv = bv[c];
    float accq = bq[c];

    #pragma unroll
    for (int i = 0; i < 3; i++) {
        int hh = h + i - 1;
        if (hh < 0 || hh >= HH) continue;
        #pragma unroll
        for (int j = 0; j < 3; j++) {
            int ww2 = w + j - 1;
            if (ww2 < 0 || ww2 >= WW) continue;
            float xh = ph[hh*WW + ww2];
            float xl = pl[hh*WW + ww2];
            int t = c*9 + i*3 + j;
            acck += xh * wk[t];
            accv += xh * wv[t];
            accq += xl * wq[t];
        }
    }
    g_key[idx] = acck;
    g_val[idx] = accv;
    g_qry[idx] = accq;
}

// ---------------------------------------------------------------------------
// Kernel 3: channel-contracted tap maps for the gating conv.
//   s[n][o][tap][h][w] = sum_c ( q[c]*wa[o][c][tap] + k[c]*wa[o][c+128][tap] )
// Weights repacked into SMEM as [c][36] (q0[9],k0[9],q1[9],k1[9]) for LDS.128.
// ---------------------------------------------------------------------------
__global__ __launch_bounds__(128) void k_s(const float* __restrict__ wa) {
    __shared__ __align__(16) float swa[CH*36];   // 18 KB

    int tid = threadIdx.x;
    for (int j = tid; j < CH*36; j += 128) {
        int c   = j / 36;
        int r   = j % 36;
        int grp = r / 9;             // 0:q/o0 1:k/o0 2:q/o1 3:k/o1
        int t   = r % 9;
        int o   = grp >> 1;
        int ci  = (grp & 1) ? (c + CH) : c;
        swa[j] = wa[(o*2*CH + ci)*9 + t];
    }
    __syncthreads();

    int px = blockIdx.x * 128 + tid;              // (n,h,w)
    int w = px & (WW-1);
    int h = (px >> 7) & (HH-1);
    int n = px >> 14;

    float acc[18];
    #pragma unroll
    for (int t = 0; t < 18; t++) acc[t] = 0.f;

    int base = (n*CH) * PLANE + h*WW + w;
    for (int c = 0; c < CH; c++) {
        float q  = g_qry[base + c*PLANE];
        float kk = g_key[base + c*PLANE];

        float wreg[36];
        float4* wr4 = (float4*)wreg;
        const float4* sp = (const float4*)(swa + c*36);
        #pragma unroll
        for (int i = 0; i < 9; i++) wr4[i] = sp[i];

        #pragma unroll
        for (int t = 0; t < 9; t++) {
            acc[t]     += q * wreg[t]      + kk * wreg[9+t];
            acc[9 + t] += q * wreg[18+t]   + kk * wreg[27+t];
        }
    }

    int pix = h*WW + w;
    #pragma unroll
    for (int o = 0; o < 2; o++)
        #pragma unroll
        for (int t = 0; t < 9; t++)
            g_s[(((n*2 + o)*9 + t) << 14) + pix] = acc[o*9 + t];
}

// ---------------------------------------------------------------------------
// Kernel 4: dyn = sigmoid( ba[o] + sum_tap shift(s[o][tap]) )
// ---------------------------------------------------------------------------
__global__ void k_dyn(const float* __restrict__ ba) {
    int idx = blockIdx.x * blockDim.x + threadIdx.x;   // (n,o,h,w)
    int w = idx & (WW-1);
    int h = (idx >> 7) & (HH-1);
    int o = (idx >> 14) & 1;
    int n = idx >> 15;

    float acc = ba[o];
    #pragma unroll
    for (int i = 0; i < 3; i++) {
        int hh = h + i - 1;
        if (hh < 0 || hh >= HH) continue;
        #pragma unroll
        for (int j = 0; j < 3; j++) {
            int ww2 = w + j - 1;
            if (ww2 < 0 || ww2 >= WW) continue;
            acc += g_s[(((n*2 + o)*9 + (i*3 + j)) << 14) + hh*WW + ww2];
        }
    }
    g_dyn[idx] = 1.f / (1.f + __expf(-acc));
}

// ---------------------------------------------------------------------------
// Kernel 5: 5x5 window attention + output fuse.
// Tile 32x8 pixels / 256 threads (warp = one pixel row -> conflict-free SMEM).
// ---------------------------------------------------------------------------
#define TW 32
#define TH 8
#define CC 8
#define HALO_W (TW+4)
#define HALO_H (TH+4)

__global__ __launch_bounds__(256) void k_attn(float* __restrict__ out) {
    __shared__ float stile[CC][HALO_H][HALO_W];   // 8*12*36*4 = 13.8 KB

    int tx = threadIdx.x & (TW-1);
    int ty = threadIdx.x >> 5;
    int w0 = blockIdx.x * TW;
    int h0 = blockIdx.y * TH;
    int n  = blockIdx.z;
    int h  = h0 + ty;
    int w  = w0 + tx;
    int pix = h*WW + w;

    float sim[25];
    #pragma unroll
    for (int k = 0; k < 25; k++) sim[k] = 0.f;

    const int TILE_ELEMS = CC * HALO_H * HALO_W;   // 3456

    // ---- Pass 1: similarity ----
    for (int c0 = 0; c0 < CH; c0 += CC) {
        __syncthreads();
        for (int i = threadIdx.x; i < TILE_ELEMS; i += 256) {
            int c  = i / (HALO_H*HALO_W);
            int r  = i % (HALO_H*HALO_W);
            int yy = r / HALO_W;
            int xx = r % HALO_W;
            int gh = h0 + yy - 2;
            int gw = w0 + xx - 2;
            float v = 0.f;
            if (gh >= 0 && gh < HH && gw >= 0 && gw < WW)
                v = g_key[((n*CH + c0 + c) << 14) + gh*WW + gw];
            stile[c][yy][xx] = v;
        }
        __syncthreads();

        #pragma unroll
        for (int c = 0; c < CC; c++) {
            float qv = g_qry[((n*CH + c0 + c) << 14) + pix];
            #pragma unroll
            for (int dy = 0; dy < 5; dy++)
                #pragma unroll
                for (int dx = 0; dx < 5; dx++)
                    sim[dy*5 + dx] += qv * stile[c][ty + dy][tx + dx];
        }
    }

    // ---- softmax over 25 taps (registers) ----
    float m = sim[0];
    #pragma unroll
    for (int k = 1; k < 25; k++) m = fmaxf(m, sim[k]);
    float ssum = 0.f;
    #pragma unroll
    for (int k = 0; k < 25; k++) { sim[k] = __expf(sim[k] - m); ssum += sim[k]; }
    float inv = 1.f / ssum;
    #pragma unroll
    for (int k = 0; k < 25; k++) sim[k] *= inv;

    float d0 = g_dyn[((n*2 + 0) << 14) + pix];
    float d1 = g_dyn[((n*2 + 1) << 14) + pix];

    // ---- Pass 2: value aggregation + fuse output ----
    for (int c0 = 0; c0 < CH; c0 += CC) {
        __syncthreads();
        for (int i = threadIdx.x; i < TILE_ELEMS; i += 256) {
            int c  = i / (HALO_H*HALO_W);
            int r  = i % (HALO_H*HALO_W);
            int yy = r / HALO_W;
            int xx = r % HALO_W;
            int gh = h0 + yy - 2;
            int gw = w0 + xx - 2;
            float v = 0.f;
            if (gh >= 0 && gh < HH && gw >= 0 && gw < WW)
                v = g_val[((n*CH + c0 + c) << 14) + gh*WW + gw];
            stile[c][yy][xx] = v;
        }
        __syncthreads();

        #pragma unroll
        for (int c = 0; c < CC; c++) {
            float acc = 0.f;
            #pragma unroll
            for (int dy = 0; dy < 5; dy++)
                #pragma unroll
                for (int dx = 0; dx < 5; dx++)
                    acc += sim[dy*5 + dx] * stile[c][ty + dy][tx + dx];
            int gi = ((n*CH + c0 + c) << 14) + pix;
            out[gi] = g_lrup[gi] + d0 * acc + d1 * g_val[gi];
        }
    }
}

// ---------------------------------------------------------------------------
extern "C" void kernel_launch(void* const* d_in, const int* in_sizes, int n_in,
                              void* d_out, int out_size) {
    const float* hr = (const float*)d_in[0];
    const float* lr = (const float*)d_in[1];
    const float* wq = (const float*)d_in[2];
    const float* bq = (const float*)d_in[3];
    const float* wk = (const float*)d_in[4];
    const float* bk = (const float*)d_in[5];
    const float* wv = (const float*)d_in[6];
    const float* bv = (const float*)d_in[7];
    const float* wa = (const float*)d_in[8];
    const float* ba = (const float*)d_in[9];
    float* out = (float*)d_out;

    // 1. bilinear upsample
    k_lrup<<<(NB*IMG)/256, 256>>>(lr);
    // 2. depthwise q/k/v
    k_qkv<<<(NB*IMG)/256, 256>>>(hr, wq, bq, wk, bk, wv, bv);
    // 3. channel-contracted gating maps
    k_s<<<(NB*PLANE)/128, 128>>>(wa);
    // 4. gate
    k_dyn<<<(NB*2*PLANE)/256, 256>>>(ba);
    // 5. window attention + output
    k_attn<<<dim3(WW/TW, HH/TH, NB), 256>>>(out);
}

// round 4
// speedup vs baseline: 1.4053x; 1.4053x over previous
#include <cuda_runtime.h>
#include <math.h>

// Problem constants (fixed shapes from setup_inputs)
#define NB 2
#define CH 128
#define HH 128
#define WW 128
#define HL 64
#define WL 64
#define PLANE (HH*WW)          // 16384
#define IMG   (CH*PLANE)

// Scratch (module-load allocated; no runtime allocs)
__device__ float g_lrup[NB*IMG];
__device__ float g_key [NB*IMG];
__device__ float g_val [NB*IMG];
__device__ float g_qry [NB*IMG];
__device__ float g_s   [NB*2*9*PLANE];     // s[n][o][tap][h][w]
__device__ float g_dyn [NB*2*PLANE];       // dyn[n][o][h][w]
__device__ float g_psim[NB*4*25*PLANE];    // partial sims [n][g][k][pix] (13MB)
__device__ float g_w   [NB*25*PLANE];      // final gated weights [n][k][pix]

// ---------------------------------------------------------------------------
// Kernel 1: bilinear upsample (align_corners=True) 64x64 -> 128x128
// ---------------------------------------------------------------------------
__global__ void k_lrup(const float* __restrict__ lr) {
    int idx = blockIdx.x * blockDim.x + threadIdx.x;   // (nc, h, w)
    int w  = idx & (WW-1);
    int h  = (idx >> 7) & (HH-1);
    int nc = idx >> 14;

    float ys = (float)(h * (HL-1)) / (float)(HH-1);
    float xs = (float)(w * (WL-1)) / (float)(WW-1);
    int y0 = (int)floorf(ys);
    int x0 = (int)floorf(xs);
    int y1 = min(y0 + 1, HL-1);
    int x1 = min(x0 + 1, WL-1);
    float wy = ys - (float)y0;
    float wx = xs - (float)x0;

    const float* p = lr + nc * (HL*WL);
    float a = p[y0*WL + x0];
    float b = p[y0*WL + x1];
    float c = p[y1*WL + x0];
    float d = p[y1*WL + x1];
    float top = a + (b - a) * wx;
    float bot = c + (d - c) * wx;
    g_lrup[idx] = top + (bot - top) * wy;
}

// ---------------------------------------------------------------------------
// Kernel 2: three depthwise 3x3 convs (key/value from hr_feat; query from lr_up)
// ---------------------------------------------------------------------------
__global__ void k_qkv(const float* __restrict__ hr,
                      const float* __restrict__ wq, const float* __restrict__ bq,
                      const float* __restrict__ wk, const float* __restrict__ bk,
                      const float* __restrict__ wv, const float* __restrict__ bv) {
    int idx = blockIdx.x * blockDim.x + threadIdx.x;   // (n, c, h, w)
    int w = idx & (WW-1);
    int h = (idx >> 7) & (HH-1);
    int c = (idx >> 14) & (CH-1);
    int n = idx >> 21;

    const float* ph = hr     + (n*CH + c) * PLANE;
    const float* pl = g_lrup + (n*CH + c) * PLANE;

    float acck = bk[c];
    float accv = bv[c];
    float accq = bq[c];

    #pragma unroll
    for (int i = 0; i < 3; i++) {
        int hh = h + i - 1;
        if (hh < 0 || hh >= HH) continue;
        #pragma unroll
        for (int j = 0; j < 3; j++) {
            int ww2 = w + j - 1;
            if (ww2 < 0 || ww2 >= WW) continue;
            float xh = ph[hh*WW + ww2];
            float xl = pl[hh*WW + ww2];
            int t = c*9 + i*3 + j;
            acck += xh * wk[t];
            accv += xh * wv[t];
            accq += xl * wq[t];
        }
    }
    g_key[idx] = acck;
    g_val[idx] = accv;
    g_qry[idx] = accq;
}

// ---------------------------------------------------------------------------
// Kernel 3: channel-contracted tap maps for the gating conv, 2 pixels/thread.
//   s[n][o][tap][h][w] = sum_c ( q[c]*wa[o][c][tap] + k[c]*wa[o][c+128][tap] )
// ---------------------------------------------------------------------------
__global__ __launch_bounds__(128) void k_s(const float* __restrict__ wa) {
    __shared__ __align__(16) float swa[CH*36];   // 18 KB

    int tid = threadIdx.x;
    for (int j = tid; j < CH*36; j += 128) {
        int c   = j / 36;
        int r   = j % 36;
        int grp = r / 9;             // 0:q/o0 1:k/o0 2:q/o1 3:k/o1
        int t   = r % 9;
        int o   = grp >> 1;
        int ci  = (grp & 1) ? (c + CH) : c;
        swa[j] = wa[(o*2*CH + ci)*9 + t];
    }
    __syncthreads();

    int px0 = blockIdx.x * 256 + tid;           // pixel A
    int px1 = px0 + 128;                        // pixel B
    int n   = px0 >> 14;                        // both pixels in same n (256|16384)
    int pixA = px0 & (PLANE-1);
    int pixB = px1 & (PLANE-1);

    float accA[18], accB[18];
    #pragma unroll
    for (int t = 0; t < 18; t++) { accA[t] = 0.f; accB[t] = 0.f; }

    int baseA = n*CH*PLANE + pixA;
    int baseB = n*CH*PLANE + pixB;
    for (int c = 0; c < CH; c++) {
        float qA = g_qry[baseA + c*PLANE];
        float kA = g_key[baseA + c*PLANE];
        float qB = g_qry[baseB + c*PLANE];
        float kB = g_key[baseB + c*PLANE];

        float wreg[36];
        float4* wr4 = (float4*)wreg;
        const float4* sp = (const float4*)(swa + c*36);
        #pragma unroll
        for (int i = 0; i < 9; i++) wr4[i] = sp[i];

        #pragma unroll
        for (int t = 0; t < 9; t++) {
            accA[t]     += qA * wreg[t]    + kA * wreg[9+t];
            accA[9 + t] += qA * wreg[18+t] + kA * wreg[27+t];
            accB[t]     += qB * wreg[t]    + kB * wreg[9+t];
            accB[9 + t] += qB * wreg[18+t] + kB * wreg[27+t];
        }
    }

    #pragma unroll
    for (int o = 0; o < 2; o++)
        #pragma unroll
        for (int t = 0; t < 9; t++) {
            int s = ((n*2 + o)*9 + t) << 14;
            g_s[s + pixA] = accA[o*9 + t];
            g_s[s + pixB] = accB[o*9 + t];
        }
}

// ---------------------------------------------------------------------------
// Kernel 4: dyn = sigmoid( ba[o] + sum_tap shift(s[o][tap]) )
// ---------------------------------------------------------------------------
__global__ void k_dyn(const float* __restrict__ ba) {
    int idx = blockIdx.x * blockDim.x + threadIdx.x;   // (n,o,h,w)
    int w = idx & (WW-1);
    int h = (idx >> 7) & (HH-1);
    int o = (idx >> 14) & 1;
    int n = idx >> 15;

    float acc = ba[o];
    #pragma unroll
    for (int i = 0; i < 3; i++) {
        int hh = h + i - 1;
        if (hh < 0 || hh >= HH) continue;
        #pragma unroll
        for (int j = 0; j < 3; j++) {
            int ww2 = w + j - 1;
            if (ww2 < 0 || ww2 >= WW) continue;
            acc += g_s[(((n*2 + o)*9 + (i*3 + j)) << 14) + hh*WW + ww2];
        }
    }
    g_dyn[idx] = 1.f / (1.f + __expf(-acc));
}

// ---------------------------------------------------------------------------
// Kernel 5: partial similarities over a 32-channel group.
// Tile 32x8 / 256 threads. grid z = n*4 + group.
// ---------------------------------------------------------------------------
#define TW 32
#define TH 8
#define HALO_W (TW+4)
#define HALO_H (TH+4)
#define CCS 8                       // channels per smem chunk
#define GSIM 32                     // channels per sim block

__global__ __launch_bounds__(256) void k_sim() {
    __shared__ float stile[CCS][HALO_H][HALO_W];   // 13.8 KB

    int tx = threadIdx.x & (TW-1);
    int ty = threadIdx.x >> 5;
    int w0 = blockIdx.x * TW;
    int h0 = blockIdx.y * TH;
    int g  = blockIdx.z & 3;
    int n  = blockIdx.z >> 2;
    int h  = h0 + ty;
    int w  = w0 + tx;
    int pix = h*WW + w;

    float sim[25];
    #pragma unroll
    for (int k = 0; k < 25; k++) sim[k] = 0.f;

    const int TILE_ELEMS = CCS * HALO_H * HALO_W;

    for (int cc = 0; cc < GSIM; cc += CCS) {
        int c0 = g*GSIM + cc;
        __syncthreads();
        for (int i = threadIdx.x; i < TILE_ELEMS; i += 256) {
            int c  = i / (HALO_H*HALO_W);
            int r  = i % (HALO_H*HALO_W);
            int yy = r / HALO_W;
            int xx = r % HALO_W;
            int gh = h0 + yy - 2;
            int gw = w0 + xx - 2;
            float v = 0.f;
            if (gh >= 0 && gh < HH && gw >= 0 && gw < WW)
                v = g_key[((n*CH + c0 + c) << 14) + gh*WW + gw];
            stile[c][yy][xx] = v;
        }
        __syncthreads();

        #pragma unroll
        for (int c = 0; c < CCS; c++) {
            float qv = g_qry[((n*CH + c0 + c) << 14) + pix];
            #pragma unroll
            for (int dy = 0; dy < 5; dy++)
                #pragma unroll
                for (int dx = 0; dx < 5; dx++)
                    sim[dy*5 + dx] += qv * stile[c][ty + dy][tx + dx];
        }
    }

    #pragma unroll
    for (int k = 0; k < 25; k++)
        g_psim[(((n*4 + g)*25 + k) << 14) + pix] = sim[k];
}

// ---------------------------------------------------------------------------
// Kernel 6: reduce partials, softmax over 25 taps, fold gates into weights.
//   w = d0 * softmax(sim);  w[12] += d1
// ---------------------------------------------------------------------------
__global__ void k_smax() {
    int idx = blockIdx.x * blockDim.x + threadIdx.x;   // (n, pix)
    int pix = idx & (PLANE-1);
    int n   = idx >> 14;

    float s[25];
    #pragma unroll
    for (int k = 0; k < 25; k++) {
        float acc = 0.f;
        #pragma unroll
        for (int g = 0; g < 4; g++)
            acc += g_psim[(((n*4 + g)*25 + k) << 14) + pix];
        s[k] = acc;
    }

    float m = s[0];
    #pragma unroll
    for (int k = 1; k < 25; k++) m = fmaxf(m, s[k]);
    float ssum = 0.f;
    #pragma unroll
    for (int k = 0; k < 25; k++) { s[k] = __expf(s[k] - m); ssum += s[k]; }

    float d0 = g_dyn[((n*2 + 0) << 14) + pix];
    float d1 = g_dyn[((n*2 + 1) << 14) + pix];
    float scale = d0 / ssum;
    #pragma unroll
    for (int k = 0; k < 25; k++) {
        float wv = s[k] * scale;
        if (k == 12) wv += d1;
        g_w[((n*25 + k) << 14) + pix] = wv;
    }
}

// ---------------------------------------------------------------------------
// Kernel 7: value aggregation over a 16-channel group + fused output.
//   out = lr_up + sum_k w[k] * v_window[k]
// ---------------------------------------------------------------------------
#define CCA 16                      // channels per agg block

__global__ __launch_bounds__(256) void k_agg(float* __restrict__ out) {
    __shared__ float stile[CCA][HALO_H][HALO_W];   // 27.6 KB

    int tx = threadIdx.x & (TW-1);
    int ty = threadIdx.x >> 5;
    int w0 = blockIdx.x * TW;
    int h0 = blockIdx.y * TH;
    int g  = blockIdx.z & 7;
    int n  = blockIdx.z >> 3;
    int c0 = g * CCA;
    int h  = h0 + ty;
    int w  = w0 + tx;
    int pix = h*WW + w;

    // weights for this pixel (coalesced per-tap slices)
    float wgt[25];
    #pragma unroll
    for (int k = 0; k < 25; k++)
        wgt[k] = g_w[((n*25 + k) << 14) + pix];

    const int TILE_ELEMS = CCA * HALO_H * HALO_W;
    for (int i = threadIdx.x; i < TILE_ELEMS; i += 256) {
        int c  = i / (HALO_H*HALO_W);
        int r  = i % (HALO_H*HALO_W);
        int yy = r / HALO_W;
        int xx = r % HALO_W;
        int gh = h0 + yy - 2;
        int gw = w0 + xx - 2;
        float v = 0.f;
        if (gh >= 0 && gh < HH && gw >= 0 && gw < WW)
            v = g_val[((n*CH + c0 + c) << 14) + gh*WW + gw];
        stile[c][yy][xx] = v;
    }
    __syncthreads();

    #pragma unroll
    for (int c = 0; c < CCA; c++) {
        float acc = 0.f;
        #pragma unroll
        for (int dy = 0; dy < 5; dy++)
            #pragma unroll
            for (int dx = 0; dx < 5; dx++)
                acc += wgt[dy*5 + dx] * stile[c][ty + dy][tx + dx];
        int gi = ((n*CH + c0 + c) << 14) + pix;
        out[gi] = g_lrup[gi] + acc;
    }
}

// ---------------------------------------------------------------------------
extern "C" void kernel_launch(void* const* d_in, const int* in_sizes, int n_in,
                              void* d_out, int out_size) {
    const float* hr = (const float*)d_in[0];
    const float* lr = (const float*)d_in[1];
    const float* wq = (const float*)d_in[2];
    const float* bq = (const float*)d_in[3];
    const float* wk = (const float*)d_in[4];
    const float* bk = (const float*)d_in[5];
    const float* wv = (const float*)d_in[6];
    const float* bv = (const float*)d_in[7];
    const float* wa = (const float*)d_in[8];
    const float* ba = (const float*)d_in[9];
    float* out = (float*)d_out;

    k_lrup<<<(NB*IMG)/256, 256>>>(lr);
    k_qkv <<<(NB*IMG)/256, 256>>>(hr, wq, bq, wk, bk, wv, bv);
    k_s   <<<(NB*PLANE)/256, 128>>>(wa);
    k_dyn <<<(NB*2*PLANE)/256, 256>>>(ba);
    k_sim <<<dim3(WW/TW, HH/TH, NB*4), 256>>>();
    k_smax<<<(NB*PLANE)/256, 256>>>();
    k_agg <<<dim3(WW/TW, HH/TH, NB*8), 256>>>(out);
}

// round 5
// speedup vs baseline: 1.4846x; 1.0564x over previous
#include <cuda_runtime.h>
#include <math.h>

// Problem constants (fixed shapes from setup_inputs)
#define NB 2
#define CH 128
#define HH 128
#define WW 128
#define HL 64
#define WL 64
#define PLANE (HH*WW)          // 16384
#define IMG   (CH*PLANE)

// Scratch (module-load allocated; no runtime allocs)
__device__ float g_lrup[NB*IMG];
__device__ float g_key [NB*IMG];
__device__ float g_val [NB*IMG];
__device__ float g_qry [NB*IMG];
__device__ float g_s   [NB*2*9*PLANE];     // s[n][o][tap][h][w]
__device__ float g_dyn [NB*2*PLANE];       // dyn[n][o][h][w]
__device__ float g_psim[NB*4*25*PLANE];    // partial sims [n][g][k][pix]
__device__ float g_w   [NB*25*PLANE];      // final gated weights [n][k][pix]

// ---------------------------------------------------------------------------
// Kernel 1: bilinear upsample (align_corners=True) 64x64 -> 128x128
// ---------------------------------------------------------------------------
__global__ void k_lrup(const float* __restrict__ lr) {
    int idx = blockIdx.x * blockDim.x + threadIdx.x;
    int w  = idx & (WW-1);
    int h  = (idx >> 7) & (HH-1);
    int nc = idx >> 14;

    float ys = (float)(h * (HL-1)) / (float)(HH-1);
    float xs = (float)(w * (WL-1)) / (float)(WW-1);
    int y0 = (int)floorf(ys);
    int x0 = (int)floorf(xs);
    int y1 = min(y0 + 1, HL-1);
    int x1 = min(x0 + 1, WL-1);
    float wy = ys - (float)y0;
    float wx = xs - (float)x0;

    const float* p = lr + nc * (HL*WL);
    float a = p[y0*WL + x0];
    float b = p[y0*WL + x1];
    float c = p[y1*WL + x0];
    float d = p[y1*WL + x1];
    float top = a + (b - a) * wx;
    float bot = c + (d - c) * wx;
    g_lrup[idx] = top + (bot - top) * wy;
}

// ---------------------------------------------------------------------------
// Kernel 2: three depthwise 3x3 convs, 4 vertical pixels per thread.
// ---------------------------------------------------------------------------
__global__ __launch_bounds__(256) void k_qkv(const float* __restrict__ hr,
                      const float* __restrict__ wq, const float* __restrict__ bq,
                      const float* __restrict__ wk, const float* __restrict__ bk,
                      const float* __restrict__ wv, const float* __restrict__ bv) {
    int idx = blockIdx.x * blockDim.x + threadIdx.x;   // (n, c, h4, w)
    int w  = idx & (WW-1);
    int h4 = (idx >> 7) & 31;
    int c  = (idx >> 12) & (CH-1);
    int n  = idx >> 19;
    int h0 = h4 * 4;

    const float* ph = hr     + (n*CH + c) * PLANE;
    const float* pl = g_lrup + (n*CH + c) * PLANE;

    float xh[6][3], xl[6][3];
    #pragma unroll
    for (int i = 0; i < 6; i++) {
        int hh = h0 + i - 1;
        bool hv = (hh >= 0) && (hh < HH);
        #pragma unroll
        for (int j = 0; j < 3; j++) {
            int wc = w + j - 1;
            bool v = hv && (wc >= 0) && (wc < WW);
            xh[i][j] = v ? ph[hh*WW + wc] : 0.f;
            xl[i][j] = v ? pl[hh*WW + wc] : 0.f;
        }
    }

    float wkr[9], wvr[9], wqr[9];
    #pragma unroll
    for (int t = 0; t < 9; t++) {
        wkr[t] = wk[c*9 + t];
        wvr[t] = wv[c*9 + t];
        wqr[t] = wq[c*9 + t];
    }
    float bkc = bk[c], bvc = bv[c], bqc = bq[c];

    #pragma unroll
    for (int p = 0; p < 4; p++) {
        float acck = bkc, accv = bvc, accq = bqc;
        #pragma unroll
        for (int i = 0; i < 3; i++)
            #pragma unroll
            for (int j = 0; j < 3; j++) {
                acck += xh[p+i][j] * wkr[i*3+j];
                accv += xh[p+i][j] * wvr[i*3+j];
                accq += xl[p+i][j] * wqr[i*3+j];
            }
        int gi = ((n*CH + c) << 14) + (h0 + p)*WW + w;
        g_key[gi] = acck;
        g_val[gi] = accv;
        g_qry[gi] = accq;
    }
}

// ---------------------------------------------------------------------------
// Kernel 3: channel-contracted tap maps for the gating conv, 2 px/thread.
// ---------------------------------------------------------------------------
__global__ __launch_bounds__(128) void k_s(const float* __restrict__ wa) {
    __shared__ __align__(16) float swa[CH*36];

    int tid = threadIdx.x;
    for (int j = tid; j < CH*36; j += 128) {
        int c   = j / 36;
        int r   = j % 36;
        int grp = r / 9;
        int t   = r % 9;
        int o   = grp >> 1;
        int ci  = (grp & 1) ? (c + CH) : c;
        swa[j] = wa[(o*2*CH + ci)*9 + t];
    }
    __syncthreads();

    int px0 = blockIdx.x * 256 + tid;
    int px1 = px0 + 128;
    int n   = px0 >> 14;
    int pixA = px0 & (PLANE-1);
    int pixB = px1 & (PLANE-1);

    float accA[18], accB[18];
    #pragma unroll
    for (int t = 0; t < 18; t++) { accA[t] = 0.f; accB[t] = 0.f; }

    int baseA = n*CH*PLANE + pixA;
    int baseB = n*CH*PLANE + pixB;
    for (int c = 0; c < CH; c++) {
        float qA = g_qry[baseA + c*PLANE];
        float kA = g_key[baseA + c*PLANE];
        float qB = g_qry[baseB + c*PLANE];
        float kB = g_key[baseB + c*PLANE];

        float wreg[36];
        float4* wr4 = (float4*)wreg;
        const float4* sp = (const float4*)(swa + c*36);
        #pragma unroll
        for (int i = 0; i < 9; i++) wr4[i] = sp[i];

        #pragma unroll
        for (int t = 0; t < 9; t++) {
            accA[t]     += qA * wreg[t]    + kA * wreg[9+t];
            accA[9 + t] += qA * wreg[18+t] + kA * wreg[27+t];
            accB[t]     += qB * wreg[t]    + kB * wreg[9+t];
            accB[9 + t] += qB * wreg[18+t] + kB * wreg[27+t];
        }
    }

    #pragma unroll
    for (int o = 0; o < 2; o++)
        #pragma unroll
        for (int t = 0; t < 9; t++) {
            int s = ((n*2 + o)*9 + t) << 14;
            g_s[s + pixA] = accA[o*9 + t];
            g_s[s + pixB] = accB[o*9 + t];
        }
}

// ---------------------------------------------------------------------------
// Kernel 4: dyn = sigmoid( ba[o] + sum_tap shift(s[o][tap]) )
// ---------------------------------------------------------------------------
__global__ void k_dyn(const float* __restrict__ ba) {
    int idx = blockIdx.x * blockDim.x + threadIdx.x;
    int w = idx & (WW-1);
    int h = (idx >> 7) & (HH-1);
    int o = (idx >> 14) & 1;
    int n = idx >> 15;

    float acc = ba[o];
    #pragma unroll
    for (int i = 0; i < 3; i++) {
        int hh = h + i - 1;
        if (hh < 0 || hh >= HH) continue;
        #pragma unroll
        for (int j = 0; j < 3; j++) {
            int ww2 = w + j - 1;
            if (ww2 < 0 || ww2 >= WW) continue;
            acc += g_s[(((n*2 + o)*9 + (i*3 + j)) << 14) + hh*WW + ww2];
        }
    }
    g_dyn[idx] = 1.f / (1.f + __expf(-acc));
}

// ---------------------------------------------------------------------------
// Kernel 5: partial similarities, 32-ch group, 64x4 tile, 2 px/thread.
// ---------------------------------------------------------------------------
#define STW 64
#define STH 4
#define SHW (STW+4)   // 68
#define SHH (STH+4)   // 8
#define CCS 8
#define GSIM 32

__global__ __launch_bounds__(128) void k_sim() {
    __shared__ __align__(16) float st[CCS][SHH][SHW];   // 17.4 KB

    int lane = threadIdx.x & 31;
    int ty   = threadIdx.x >> 5;          // warp = one pixel row
    int w0 = blockIdx.x * STW;
    int h0 = blockIdx.y * STH;
    int g  = blockIdx.z & 3;
    int n  = blockIdx.z >> 2;
    int h  = h0 + ty;
    int wA = w0 + 2*lane;
    int pixA = h*WW + wA;

    float simA[25], simB[25];
    #pragma unroll
    for (int k = 0; k < 25; k++) { simA[k] = 0.f; simB[k] = 0.f; }

    const int TE = CCS * SHH * SHW;       // 4352

    for (int cc = 0; cc < GSIM; cc += CCS) {
        int c0 = g*GSIM + cc;
        __syncthreads();
        for (int i = threadIdx.x; i < TE; i += 128) {
            int c  = i / (SHH*SHW);
            int r  = i % (SHH*SHW);
            int yy = r / SHW;
            int xx = r % SHW;
            int gh = h0 + yy - 2;
            int gw = w0 + xx - 2;
            float v = 0.f;
            if (gh >= 0 && gh < HH && gw >= 0 && gw < WW)
                v = g_key[((n*CH + c0 + c) << 14) + gh*WW + gw];
            st[c][yy][xx] = v;
        }
        __syncthreads();

        #pragma unroll
        for (int c = 0; c < CCS; c++) {
            float2 q2 = *(const float2*)&g_qry[((n*CH + c0 + c) << 14) + pixA];
            #pragma unroll
            for (int dy = 0; dy < 5; dy++) {
                float2 t0 = *(float2*)&st[c][ty+dy][2*lane + 0];
                float2 t1 = *(float2*)&st[c][ty+dy][2*lane + 2];
                float2 t2 = *(float2*)&st[c][ty+dy][2*lane + 4];
                simA[dy*5+0] += q2.x * t0.x;
                simA[dy*5+1] += q2.x * t0.y;
                simA[dy*5+2] += q2.x * t1.x;
                simA[dy*5+3] += q2.x * t1.y;
                simA[dy*5+4] += q2.x * t2.x;
                simB[dy*5+0] += q2.y * t0.y;
                simB[dy*5+1] += q2.y * t1.x;
                simB[dy*5+2] += q2.y * t1.y;
                simB[dy*5+3] += q2.y * t2.x;
                simB[dy*5+4] += q2.y * t2.y;
            }
        }
    }

    #pragma unroll
    for (int k = 0; k < 25; k++) {
        float2 o; o.x = simA[k]; o.y = simB[k];
        *(float2*)&g_psim[(((n*4 + g)*25 + k) << 14) + pixA] = o;
    }
}

// ---------------------------------------------------------------------------
// Kernel 6: reduce partials, softmax over 25 taps, fold gates into weights.
// ---------------------------------------------------------------------------
__global__ void k_smax() {
    int idx = blockIdx.x * blockDim.x + threadIdx.x;
    int pix = idx & (PLANE-1);
    int n   = idx >> 14;

    float s[25];
    #pragma unroll
    for (int k = 0; k < 25; k++) {
        float acc = 0.f;
        #pragma unroll
        for (int g = 0; g < 4; g++)
            acc += g_psim[(((n*4 + g)*25 + k) << 14) + pix];
        s[k] = acc;
    }

    float m = s[0];
    #pragma unroll
    for (int k = 1; k < 25; k++) m = fmaxf(m, s[k]);
    float ssum = 0.f;
    #pragma unroll
    for (int k = 0; k < 25; k++) { s[k] = __expf(s[k] - m); ssum += s[k]; }

    float d0 = g_dyn[((n*2 + 0) << 14) + pix];
    float d1 = g_dyn[((n*2 + 1) << 14) + pix];
    float scale = d0 / ssum;
    #pragma unroll
    for (int k = 0; k < 25; k++) {
        float wv = s[k] * scale;
        if (k == 12) wv += d1;
        g_w[((n*25 + k) << 14) + pix] = wv;
    }
}

// ---------------------------------------------------------------------------
// Kernel 7: value aggregation, 16-ch group, 64x4 tile, 2 px/thread.
// ---------------------------------------------------------------------------
#define CCA 16

__global__ __launch_bounds__(128) void k_agg(float* __restrict__ out) {
    __shared__ __align__(16) float st[CCA][SHH][SHW];   // 34.8 KB

    int lane = threadIdx.x & 31;
    int ty   = threadIdx.x >> 5;
    int w0 = blockIdx.x * STW;
    int h0 = blockIdx.y * STH;
    int g  = blockIdx.z & 7;
    int n  = blockIdx.z >> 3;
    int c0 = g * CCA;
    int h  = h0 + ty;
    int wA = w0 + 2*lane;
    int pixA = h*WW + wA;

    float wgtA[25], wgtB[25];
    #pragma unroll
    for (int k = 0; k < 25; k++) {
        float2 wv = *(const float2*)&g_w[((n*25 + k) << 14) + pixA];
        wgtA[k] = wv.x; wgtB[k] = wv.y;
    }

    const int TE = CCA * SHH * SHW;       // 8704
    for (int i = threadIdx.x; i < TE; i += 128) {
        int c  = i / (SHH*SHW);
        int r  = i % (SHH*SHW);
        int yy = r / SHW;
        int xx = r % SHW;
        int gh = h0 + yy - 2;
        int gw = w0 + xx - 2;
        float v = 0.f;
        if (gh >= 0 && gh < HH && gw >= 0 && gw < WW)
            v = g_val[((n*CH + c0 + c) << 14) + gh*WW + gw];
        st[c][yy][xx] = v;
    }
    __syncthreads();

    #pragma unroll
    for (int c = 0; c < CCA; c++) {
        float accA = 0.f, accB = 0.f;
        #pragma unroll
        for (int dy = 0; dy < 5; dy++) {
            float2 t0 = *(float2*)&st[c][ty+dy][2*lane + 0];
            float2 t1 = *(float2*)&st[c][ty+dy][2*lane + 2];
            float2 t2 = *(float2*)&st[c][ty+dy][2*lane + 4];
            accA += wgtA[dy*5+0]*t0.x + wgtA[dy*5+1]*t0.y + wgtA[dy*5+2]*t1.x
                  + wgtA[dy*5+3]*t1.y + wgtA[dy*5+4]*t2.x;
            accB += wgtB[dy*5+0]*t0.y + wgtB[dy*5+1]*t1.x + wgtB[dy*5+2]*t1.y
                  + wgtB[dy*5+3]*t2.x + wgtB[dy*5+4]*t2.y;
        }
        int gi = ((n*CH + c0 + c) << 14) + pixA;
        float2 lu = *(const float2*)&g_lrup[gi];
        float2 o; o.x = lu.x + accA; o.y = lu.y + accB;
        *(float2*)&out[gi] = o;
    }
}

// ---------------------------------------------------------------------------
extern "C" void kernel_launch(void* const* d_in, const int* in_sizes, int n_in,
                              void* d_out, int out_size) {
    const float* hr = (const float*)d_in[0];
    const float* lr = (const float*)d_in[1];
    const float* wq = (const float*)d_in[2];
    const float* bq = (const float*)d_in[3];
    const float* wk = (const float*)d_in[4];
    const float* bk = (const float*)d_in[5];
    const float* wv = (const float*)d_in[6];
    const float* bv = (const float*)d_in[7];
    const float* wa = (const float*)d_in[8];
    const float* ba = (const float*)d_in[9];
    float* out = (float*)d_out;

    k_lrup<<<(NB*IMG)/256, 256>>>(lr);
    k_qkv <<<(NB*IMG/4)/256, 256>>>(hr, wq, bq, wk, bk, wv, bv);
    k_s   <<<(NB*PLANE)/256, 128>>>(wa);
    // k_sim placed 4th so the fixed ncu skip window lands on it
    k_sim <<<dim3(WW/STW, HH/STH, NB*4), 128>>>();
    k_dyn <<<(NB*2*PLANE)/256, 256>>>(ba);
    k_smax<<<(NB*PLANE)/256, 256>>>();
    k_agg <<<dim3(WW/STW, HH/STH, NB*8), 128>>>(out);
}

// round 6
// speedup vs baseline: 1.5201x; 1.0239x over previous
#include <cuda_runtime.h>
#include <math.h>

// Problem constants (fixed shapes from setup_inputs)
#define NB 2
#define CH 128
#define HH 128
#define WW 128
#define HL 64
#define WL 64
#define PLANE (HH*WW)          // 16384
#define IMG   (CH*PLANE)

#define NSPLIT 4               // channel splits for gating conv
#define CPS (CH/NSPLIT)        // 32
#define NGRP 8                 // channel groups for sim
#define GSIM (CH/NGRP)         // 16

// Scratch (module-load allocated; no runtime allocs)
__device__ float g_lrup[NB*IMG];
__device__ float g_key [NB*IMG];
__device__ float g_val [NB*IMG];
__device__ float g_qry [NB*IMG];
__device__ float g_s4  [NSPLIT*NB*2*9*PLANE];   // partial gating tap maps
__device__ float g_dyn [NB*2*PLANE];
__device__ float g_psim[NB*NGRP*25*PLANE];      // partial sims (26MB)
__device__ float g_w   [NB*25*PLANE];           // gated softmax weights

// ---------------------------------------------------------------------------
// Kernel 1: bilinear upsample (align_corners=True) 64x64 -> 128x128
// ---------------------------------------------------------------------------
__global__ void k_lrup(const float* __restrict__ lr) {
    int idx = blockIdx.x * blockDim.x + threadIdx.x;
    int w  = idx & (WW-1);
    int h  = (idx >> 7) & (HH-1);
    int nc = idx >> 14;

    float ys = (float)(h * (HL-1)) / (float)(HH-1);
    float xs = (float)(w * (WL-1)) / (float)(WW-1);
    int y0 = (int)floorf(ys);
    int x0 = (int)floorf(xs);
    int y1 = min(y0 + 1, HL-1);
    int x1 = min(x0 + 1, WL-1);
    float wy = ys - (float)y0;
    float wx = xs - (float)x0;

    const float* p = lr + nc * (HL*WL);
    float a = p[y0*WL + x0];
    float b = p[y0*WL + x1];
    float c = p[y1*WL + x0];
    float d = p[y1*WL + x1];
    float top = a + (b - a) * wx;
    float bot = c + (d - c) * wx;
    g_lrup[idx] = top + (bot - top) * wy;
}

// ---------------------------------------------------------------------------
// Kernel 2: three depthwise 3x3 convs, 4 horizontal px/thread, float4 I/O.
// ---------------------------------------------------------------------------
__global__ __launch_bounds__(128) void k_qkv(const float* __restrict__ hr,
                      const float* __restrict__ wq, const float* __restrict__ bq,
                      const float* __restrict__ wk, const float* __restrict__ bk,
                      const float* __restrict__ wv, const float* __restrict__ bv) {
    int idx = blockIdx.x * 128 + threadIdx.x;   // (n, c, h, w4)
    int w4 = idx & 31;
    int h  = (idx >> 5) & (HH-1);
    int c  = (idx >> 12) & (CH-1);
    int n  = idx >> 19;
    int w0 = w4 * 4;

    const float* ph = hr     + (n*CH + c) * PLANE;
    const float* pl = g_lrup + (n*CH + c) * PLANE;

    float xh[3][6], xl[3][6];
    #pragma unroll
    for (int i = 0; i < 3; i++) {
        int hh = h + i - 1;
        bool hv = (hh >= 0) && (hh < HH);
        if (hv) {
            int rb = hh * WW;
            float lh = (w0 - 1 >= 0) ? ph[rb + w0 - 1] : 0.f;
            float ll = (w0 - 1 >= 0) ? pl[rb + w0 - 1] : 0.f;
            float4 mh = *(const float4*)&ph[rb + w0];
            float4 ml = *(const float4*)&pl[rb + w0];
            float rh = (w0 + 4 < WW) ? ph[rb + w0 + 4] : 0.f;
            float rl = (w0 + 4 < WW) ? pl[rb + w0 + 4] : 0.f;
            xh[i][0]=lh; xh[i][1]=mh.x; xh[i][2]=mh.y; xh[i][3]=mh.z; xh[i][4]=mh.w; xh[i][5]=rh;
            xl[i][0]=ll; xl[i][1]=ml.x; xl[i][2]=ml.y; xl[i][3]=ml.z; xl[i][4]=ml.w; xl[i][5]=rl;
        } else {
            #pragma unroll
            for (int j = 0; j < 6; j++) { xh[i][j] = 0.f; xl[i][j] = 0.f; }
        }
    }

    float wkr[9], wvr[9], wqr[9];
    #pragma unroll
    for (int t = 0; t < 9; t++) {
        wkr[t] = wk[c*9 + t];
        wvr[t] = wv[c*9 + t];
        wqr[t] = wq[c*9 + t];
    }
    float bkc = bk[c], bvc = bv[c], bqc = bq[c];

    float4 ok, ov, oq;
    float* okp = (float*)&ok; float* ovp = (float*)&ov; float* oqp = (float*)&oq;
    #pragma unroll
    for (int p = 0; p < 4; p++) {
        float acck = bkc, accv = bvc, accq = bqc;
        #pragma unroll
        for (int i = 0; i < 3; i++)
            #pragma unroll
            for (int j = 0; j < 3; j++) {
                acck += xh[i][p+j] * wkr[i*3+j];
                accv += xh[i][p+j] * wvr[i*3+j];
                accq += xl[i][p+j] * wqr[i*3+j];
            }
        okp[p] = acck; ovp[p] = accv; oqp[p] = accq;
    }
    int gi = ((n*CH + c) << 14) + h*WW + w0;
    *(float4*)&g_key[gi] = ok;
    *(float4*)&g_val[gi] = ov;
    *(float4*)&g_qry[gi] = oq;
}

// ---------------------------------------------------------------------------
// Kernel 3: partial gating tap maps, 4-way channel split, 1 px/thread.
//   s4[sp][n][o][tap][pix] = sum_{c in split} q[c]*wa[o][c] + k[c]*wa[o][c+CH]
// ---------------------------------------------------------------------------
__global__ __launch_bounds__(128) void k_s(const float* __restrict__ wa) {
    __shared__ __align__(16) float swa[CPS*36];   // 4.5 KB

    int tid = threadIdx.x;
    int sp  = blockIdx.y;
    int cbase = sp * CPS;

    for (int j = tid; j < CPS*36; j += 128) {
        int c   = j / 36;
        int r   = j % 36;
        int grp = r / 9;             // 0:q/o0 1:k/o0 2:q/o1 3:k/o1
        int t   = r % 9;
        int o   = grp >> 1;
        int ci  = cbase + c + ((grp & 1) ? CH : 0);
        swa[j] = wa[(o*2*CH + ci)*9 + t];
    }
    __syncthreads();

    int px  = blockIdx.x * 128 + tid;
    int n   = px >> 14;
    int pix = px & (PLANE-1);

    float acc[18];
    #pragma unroll
    for (int t = 0; t < 18; t++) acc[t] = 0.f;

    int base = n*CH*PLANE + cbase*PLANE + pix;
    for (int c = 0; c < CPS; c += 2) {
        float q0 = g_qry[base + c*PLANE];
        float k0 = g_key[base + c*PLANE];
        float q1 = g_qry[base + (c+1)*PLANE];
        float k1 = g_key[base + (c+1)*PLANE];

        float wreg[36];
        float4* wr4 = (float4*)wreg;
        const float4* sp0 = (const float4*)(swa + c*36);
        #pragma unroll
        for (int i = 0; i < 9; i++) wr4[i] = sp0[i];
        #pragma unroll
        for (int t = 0; t < 9; t++) {
            acc[t]     += q0 * wreg[t]    + k0 * wreg[9+t];
            acc[9 + t] += q0 * wreg[18+t] + k0 * wreg[27+t];
        }
        const float4* sp1 = (const float4*)(swa + (c+1)*36);
        #pragma unroll
        for (int i = 0; i < 9; i++) wr4[i] = sp1[i];
        #pragma unroll
        for (int t = 0; t < 9; t++) {
            acc[t]     += q1 * wreg[t]    + k1 * wreg[9+t];
            acc[9 + t] += q1 * wreg[18+t] + k1 * wreg[27+t];
        }
    }

    #pragma unroll
    for (int o = 0; o < 2; o++)
        #pragma unroll
        for (int t = 0; t < 9; t++)
            g_s4[((((sp*NB + n)*2 + o)*9 + t) << 14) + pix] = acc[o*9 + t];
}

// ---------------------------------------------------------------------------
// Kernel 4: dyn = sigmoid( ba[o] + sum_sp sum_tap shift(s4) )
// ---------------------------------------------------------------------------
__global__ __launch_bounds__(128) void k_dyn(const float* __restrict__ ba) {
    int idx = blockIdx.x * 128 + threadIdx.x;   // (n,o,h,w)
    int w = idx & (WW-1);
    int h = (idx >> 7) & (HH-1);
    int o = (idx >> 14) & 1;
    int n = idx >> 15;

    float acc = ba[o];
    #pragma unroll
    for (int sp = 0; sp < NSPLIT; sp++) {
        #pragma unroll
        for (int i = 0; i < 3; i++) {
            int hh = h + i - 1;
            if (hh < 0 || hh >= HH) continue;
            #pragma unroll
            for (int j = 0; j < 3; j++) {
                int ww2 = w + j - 1;
                if (ww2 < 0 || ww2 >= WW) continue;
                acc += g_s4[((((sp*NB + n)*2 + o)*9 + (i*3 + j)) << 14) + hh*WW + ww2];
            }
        }
    }
    g_dyn[idx] = 1.f / (1.f + __expf(-acc));
}

// ---------------------------------------------------------------------------
// Kernel 5: partial similarities, 16-ch group, 64x4 tile, 2 px/thread.
// Single fill phase, div-free float2 fill, q prefetch.
// ---------------------------------------------------------------------------
#define STW 64
#define STH 4
#define SHW (STW+4)   // 68
#define SHH (STH+4)   // 8

__global__ __launch_bounds__(128) void k_sim() {
    __shared__ __align__(16) float st[GSIM][SHH][SHW];   // 34.8 KB

    int lane = threadIdx.x & 31;
    int warp = threadIdx.x >> 5;          // pixel row within tile
    int w0 = blockIdx.x * STW;
    int h0 = blockIdx.y * STH;
    int g  = blockIdx.z & (NGRP-1);
    int n  = blockIdx.z >> 3;
    int c0 = g * GSIM;
    int h  = h0 + warp;
    int wA = w0 + 2*lane;
    int pixA = h*WW + wA;

    // ---- div-free halo fill: warp -> 2 rows, lane -> float2 pairs ----
    #pragma unroll 1
    for (int c = 0; c < GSIM; c++) {
        const float* src = g_key + ((n*CH + c0 + c) << 14);
        #pragma unroll
        for (int r2 = 0; r2 < 2; r2++) {
            int yy = warp*2 + r2;
            int gh = h0 + yy - 2;
            bool hv = (gh >= 0) && (gh < HH);
            #pragma unroll
            for (int jo = 0; jo < 2; jo++) {
                int j = lane + jo*32;
                if (j < 34) {
                    int xx = 2*j;
                    int gw = w0 + xx - 2;
                    float2 v = make_float2(0.f, 0.f);
                    if (hv) {
                        if (gw >= 0 && gw + 1 < WW) {
                            v = *(const float2*)&src[gh*WW + gw];
                        } else {
                            if (gw >= 0 && gw < WW)   v.x = src[gh*WW + gw];
                            if (gw + 1 >= 0 && gw + 1 < WW) v.y = src[gh*WW + gw + 1];
                        }
                    }
                    *(float2*)&st[c][yy][xx] = v;
                }
            }
        }
    }

    // ---- q prefetch (16 independent LDG.64) ----
    float2 q2[GSIM];
    #pragma unroll
    for (int c = 0; c < GSIM; c++)
        q2[c] = *(const float2*)&g_qry[((n*CH + c0 + c) << 14) + pixA];

    __syncthreads();

    float simA[25], simB[25];
    #pragma unroll
    for (int k = 0; k < 25; k++) { simA[k] = 0.f; simB[k] = 0.f; }

    #pragma unroll
    for (int c = 0; c < GSIM; c++) {
        #pragma unroll
        for (int dy = 0; dy < 5; dy++) {
            float2 t0 = *(float2*)&st[c][warp+dy][2*lane + 0];
            float2 t1 = *(float2*)&st[c][warp+dy][2*lane + 2];
            float2 t2 = *(float2*)&st[c][warp+dy][2*lane + 4];
            simA[dy*5+0] += q2[c].x * t0.x;
            simA[dy*5+1] += q2[c].x * t0.y;
            simA[dy*5+2] += q2[c].x * t1.x;
            simA[dy*5+3] += q2[c].x * t1.y;
            simA[dy*5+4] += q2[c].x * t2.x;
            simB[dy*5+0] += q2[c].y * t0.y;
            simB[dy*5+1] += q2[c].y * t1.x;
            simB[dy*5+2] += q2[c].y * t1.y;
            simB[dy*5+3] += q2[c].y * t2.x;
            simB[dy*5+4] += q2[c].y * t2.y;
        }
    }

    #pragma unroll
    for (int k = 0; k < 25; k++) {
        float2 o; o.x = simA[k]; o.y = simB[k];
        *(float2*)&g_psim[(((n*NGRP + g)*25 + k) << 14) + pixA] = o;
    }
}

// ---------------------------------------------------------------------------
// Kernel 6: reduce 8 partials, softmax over 25 taps, fold gates.
// ---------------------------------------------------------------------------
__global__ __launch_bounds__(128) void k_smax() {
    int idx = blockIdx.x * 128 + threadIdx.x;
    int pix = idx & (PLANE-1);
    int n   = idx >> 14;

    float s[25];
    #pragma unroll
    for (int k = 0; k < 25; k++) s[k] = 0.f;
    #pragma unroll
    for (int g = 0; g < NGRP; g++)
        #pragma unroll
        for (int k = 0; k < 25; k++)
            s[k] += g_psim[(((n*NGRP + g)*25 + k) << 14) + pix];

    float m = s[0];
    #pragma unroll
    for (int k = 1; k < 25; k++) m = fmaxf(m, s[k]);
    float ssum = 0.f;
    #pragma unroll
    for (int k = 0; k < 25; k++) { s[k] = __expf(s[k] - m); ssum += s[k]; }

    float d0 = g_dyn[((n*2 + 0) << 14) + pix];
    float d1 = g_dyn[((n*2 + 1) << 14) + pix];
    float scale = d0 / ssum;
    #pragma unroll
    for (int k = 0; k < 25; k++) {
        float wv = s[k] * scale;
        if (k == 12) wv += d1;
        g_w[((n*25 + k) << 14) + pix] = wv;
    }
}

// ---------------------------------------------------------------------------
// Kernel 7: value aggregation, 16-ch group, 64x4 tile, 2 px/thread.
// ---------------------------------------------------------------------------
#define CCA 16

__global__ __launch_bounds__(128) void k_agg(float* __restrict__ out) {
    __shared__ __align__(16) float st[CCA][SHH][SHW];   // 34.8 KB

    int lane = threadIdx.x & 31;
    int warp = threadIdx.x >> 5;
    int w0 = blockIdx.x * STW;
    int h0 = blockIdx.y * STH;
    int g  = blockIdx.z & 7;
    int n  = blockIdx.z >> 3;
    int c0 = g * CCA;
    int h  = h0 + warp;
    int wA = w0 + 2*lane;
    int pixA = h*WW + wA;

    // weights for both pixels (25 independent LDG.64)
    float wgtA[25], wgtB[25];
    #pragma unroll
    for (int k = 0; k < 25; k++) {
        float2 wv = *(const float2*)&g_w[((n*25 + k) << 14) + pixA];
        wgtA[k] = wv.x; wgtB[k] = wv.y;
    }

    #pragma unroll 1
    for (int c = 0; c < CCA; c++) {
        const float* src = g_val + ((n*CH + c0 + c) << 14);
        #pragma unroll
        for (int r2 = 0; r2 < 2; r2++) {
            int yy = warp*2 + r2;
            int gh = h0 + yy - 2;
            bool hv = (gh >= 0) && (gh < HH);
            #pragma unroll
            for (int jo = 0; jo < 2; jo++) {
                int j = lane + jo*32;
                if (j < 34) {
                    int xx = 2*j;
                    int gw = w0 + xx - 2;
                    float2 v = make_float2(0.f, 0.f);
                    if (hv) {
                        if (gw >= 0 && gw + 1 < WW) {
                            v = *(const float2*)&src[gh*WW + gw];
                        } else {
                            if (gw >= 0 && gw < WW)   v.x = src[gh*WW + gw];
                            if (gw + 1 >= 0 && gw + 1 < WW) v.y = src[gh*WW + gw + 1];
                        }
                    }
                    *(float2*)&st[c][yy][xx] = v;
                }
            }
        }
    }
    __syncthreads();

    #pragma unroll
    for (int c = 0; c < CCA; c++) {
        float accA = 0.f, accB = 0.f;
        #pragma unroll
        for (int dy = 0; dy < 5; dy++) {
            float2 t0 = *(float2*)&st[c][warp+dy][2*lane + 0];
            float2 t1 = *(float2*)&st[c][warp+dy][2*lane + 2];
            float2 t2 = *(float2*)&st[c][warp+dy][2*lane + 4];
            accA += wgtA[dy*5+0]*t0.x + wgtA[dy*5+1]*t0.y + wgtA[dy*5+2]*t1.x
                  + wgtA[dy*5+3]*t1.y + wgtA[dy*5+4]*t2.x;
            accB += wgtB[dy*5+0]*t0.y + wgtB[dy*5+1]*t1.x + wgtB[dy*5+2]*t1.y
                  + wgtB[dy*5+3]*t2.x + wgtB[dy*5+4]*t2.y;
        }
        int gi = ((n*CH + c0 + c) << 14) + pixA;
        float2 lu = *(const float2*)&g_lrup[gi];
        float2 o; o.x = lu.x + accA; o.y = lu.y + accB;
        *(float2*)&out[gi] = o;
    }
}

// ---------------------------------------------------------------------------
extern "C" void kernel_launch(void* const* d_in, const int* in_sizes, int n_in,
                              void* d_out, int out_size) {
    const float* hr = (const float*)d_in[0];
    const float* lr = (const float*)d_in[1];
    const float* wq = (const float*)d_in[2];
    const float* bq = (const float*)d_in[3];
    const float* wk = (const float*)d_in[4];
    const float* bk = (const float*)d_in[5];
    const float* wv = (const float*)d_in[6];
    const float* bv = (const float*)d_in[7];
    const float* wa = (const float*)d_in[8];
    const float* ba = (const float*)d_in[9];
    float* out = (float*)d_out;

    k_lrup<<<(NB*IMG)/256, 256>>>(lr);
    k_qkv <<<(NB*IMG/4)/128, 128>>>(hr, wq, bq, wk, bk, wv, bv);
    k_s   <<<dim3((NB*PLANE)/128, NSPLIT), 128>>>(wa);
    // k_sim stays 4th so the fixed ncu window lands on it
    k_sim <<<dim3(WW/STW, HH/STH, NB*NGRP), 128>>>();
    k_dyn <<<(NB*2*PLANE)/128, 128>>>(ba);
    k_smax<<<(NB*PLANE)/128, 128>>>();
    k_agg <<<dim3(WW/STW, HH/STH, NB*8), 128>>>(out);
}

// round 9
// speedup vs baseline: 1.9452x; 1.2797x over previous
#include <cuda_runtime.h>
#include <math.h>

// Problem constants (fixed shapes from setup_inputs)
#define NB 2
#define CH 128
#define HH 128
#define WW 128
#define HL 64
#define WL 64
#define PLANE (HH*WW)          // 16384
#define IMG   (CH*PLANE)

#define NSPLIT 4               // channel splits for gating conv
#define CPS (CH/NSPLIT)        // 32
#define NGRP 8                 // channel groups for sim
#define GSIM (CH/NGRP)         // 16

// Scratch (module-load allocated; no runtime allocs)
__device__ float g_lrup[NB*IMG];
__device__ float g_key [NB*IMG];
__device__ float g_val [NB*IMG];
__device__ float g_qry [NB*IMG];
__device__ float g_s4  [NSPLIT*NB*2*9*PLANE];   // partial gating tap maps
__device__ float g_dyn [NB*2*PLANE];
__device__ float g_psim[NB*NGRP*25*PLANE];      // partial sims (26MB, L2-resident)
__device__ float g_w   [NB*25*PLANE];           // gated softmax weights

// ---------------------------------------------------------------------------
// Kernel 1: bilinear upsample (align_corners=True) 64x64 -> 128x128
// ---------------------------------------------------------------------------
__global__ void k_lrup(const float* __restrict__ lr) {
    int idx = blockIdx.x * blockDim.x + threadIdx.x;
    int w  = idx & (WW-1);
    int h  = (idx >> 7) & (HH-1);
    int nc = idx >> 14;

    float ys = (float)(h * (HL-1)) / (float)(HH-1);
    float xs = (float)(w * (WL-1)) / (float)(WW-1);
    int y0 = (int)floorf(ys);
    int x0 = (int)floorf(xs);
    int y1 = min(y0 + 1, HL-1);
    int x1 = min(x0 + 1, WL-1);
    float wy = ys - (float)y0;
    float wx = xs - (float)x0;

    const float* p = lr + nc * (HL*WL);
    float a = p[y0*WL + x0];
    float b = p[y0*WL + x1];
    float c = p[y1*WL + x0];
    float d = p[y1*WL + x1];
    float top = a + (b - a) * wx;
    float bot = c + (d - c) * wx;
    g_lrup[idx] = top + (bot - top) * wy;
}

// ---------------------------------------------------------------------------
// Kernel 2: three depthwise 3x3 convs, 4 horizontal px/thread, float4 I/O.
// ---------------------------------------------------------------------------
__global__ __launch_bounds__(128) void k_qkv(const float* __restrict__ hr,
                      const float* __restrict__ wq, const float* __restrict__ bq,
                      const float* __restrict__ wk, const float* __restrict__ bk,
                      const float* __restrict__ wv, const float* __restrict__ bv) {
    int idx = blockIdx.x * 128 + threadIdx.x;   // (n, c, h, w4)
    int w4 = idx & 31;
    int h  = (idx >> 5) & (HH-1);
    int c  = (idx >> 12) & (CH-1);
    int n  = idx >> 19;
    int w0 = w4 * 4;

    const float* ph = hr     + (n*CH + c) * PLANE;
    const float* pl = g_lrup + (n*CH + c) * PLANE;

    float xh[3][6], xl[3][6];
    #pragma unroll
    for (int i = 0; i < 3; i++) {
        int hh = h + i - 1;
        bool hv = (hh >= 0) && (hh < HH);
        if (hv) {
            int rb = hh * WW;
            float lh = (w0 - 1 >= 0) ? ph[rb + w0 - 1] : 0.f;
            float ll = (w0 - 1 >= 0) ? pl[rb + w0 - 1] : 0.f;
            float4 mh = *(const float4*)&ph[rb + w0];
            float4 ml = *(const float4*)&pl[rb + w0];
            float rh = (w0 + 4 < WW) ? ph[rb + w0 + 4] : 0.f;
            float rl = (w0 + 4 < WW) ? pl[rb + w0 + 4] : 0.f;
            xh[i][0]=lh; xh[i][1]=mh.x; xh[i][2]=mh.y; xh[i][3]=mh.z; xh[i][4]=mh.w; xh[i][5]=rh;
            xl[i][0]=ll; xl[i][1]=ml.x; xl[i][2]=ml.y; xl[i][3]=ml.z; xl[i][4]=ml.w; xl[i][5]=rl;
        } else {
            #pragma unroll
            for (int j = 0; j < 6; j++) { xh[i][j] = 0.f; xl[i][j] = 0.f; }
        }
    }

    float wkr[9], wvr[9], wqr[9];
    #pragma unroll
    for (int t = 0; t < 9; t++) {
        wkr[t] = wk[c*9 + t];
        wvr[t] = wv[c*9 + t];
        wqr[t] = wq[c*9 + t];
    }
    float bkc = bk[c], bvc = bv[c], bqc = bq[c];

    float4 ok, ov, oq;
    float* okp = (float*)&ok; float* ovp = (float*)&ov; float* oqp = (float*)&oq;
    #pragma unroll
    for (int p = 0; p < 4; p++) {
        float acck = bkc, accv = bvc, accq = bqc;
        #pragma unroll
        for (int i = 0; i < 3; i++)
            #pragma unroll
            for (int j = 0; j < 3; j++) {
                acck += xh[i][p+j] * wkr[i*3+j];
                accv += xh[i][p+j] * wvr[i*3+j];
                accq += xl[i][p+j] * wqr[i*3+j];
            }
        okp[p] = acck; ovp[p] = accv; oqp[p] = accq;
    }
    int gi = ((n*CH + c) << 14) + h*WW + w0;
    *(float4*)&g_key[gi] = ok;
    *(float4*)&g_val[gi] = ov;
    *(float4*)&g_qry[gi] = oq;
}

// ---------------------------------------------------------------------------
// Kernel 3: partial gating tap maps, 4-way channel split, 2 px/thread.
// ---------------------------------------------------------------------------
__global__ __launch_bounds__(128) void k_s(const float* __restrict__ wa) {
    __shared__ __align__(16) float swa[CPS*36];   // 4.5 KB

    int tid = threadIdx.x;
    int sp  = blockIdx.y;
    int cbase = sp * CPS;

    for (int j = tid; j < CPS*36; j += 128) {
        int c   = j / 36;
        int r   = j % 36;
        int grp = r / 9;             // 0:q/o0 1:k/o0 2:q/o1 3:k/o1
        int t   = r % 9;
        int o   = grp >> 1;
        int ci  = cbase + c + ((grp & 1) ? CH : 0);
        swa[j] = wa[(o*2*CH + ci)*9 + t];
    }
    __syncthreads();

    int px0 = blockIdx.x * 256 + tid;           // pixel A
    int px1 = px0 + 128;                        // pixel B (same n: 256|16384)
    int n   = px0 >> 14;
    int pixA = px0 & (PLANE-1);
    int pixB = px1 & (PLANE-1);

    float accA[18], accB[18];
    #pragma unroll
    for (int t = 0; t < 18; t++) { accA[t] = 0.f; accB[t] = 0.f; }

    int baseA = n*CH*PLANE + cbase*PLANE + pixA;
    int baseB = n*CH*PLANE + cbase*PLANE + pixB;
    for (int c = 0; c < CPS; c++) {
        float qA = g_qry[baseA + c*PLANE];
        float kA = g_key[baseA + c*PLANE];
        float qB = g_qry[baseB + c*PLANE];
        float kB = g_key[baseB + c*PLANE];

        float wreg[36];
        float4* wr4 = (float4*)wreg;
        const float4* sw4 = (const float4*)(swa + c*36);
        #pragma unroll
        for (int i = 0; i < 9; i++) wr4[i] = sw4[i];

        #pragma unroll
        for (int t = 0; t < 9; t++) {
            accA[t]     += qA * wreg[t]    + kA * wreg[9+t];
            accA[9 + t] += qA * wreg[18+t] + kA * wreg[27+t];
            accB[t]     += qB * wreg[t]    + kB * wreg[9+t];
            accB[9 + t] += qB * wreg[18+t] + kB * wreg[27+t];
        }
    }

    #pragma unroll
    for (int o = 0; o < 2; o++)
        #pragma unroll
        for (int t = 0; t < 9; t++) {
            int s = (((sp*NB + n)*2 + o)*9 + t) << 14;
            g_s4[s + pixA] = accA[o*9 + t];
            g_s4[s + pixB] = accB[o*9 + t];
        }
}

// ---------------------------------------------------------------------------
// Kernel 4: dyn = sigmoid( ba[o] + sum_sp sum_tap shift(s4) )
// ---------------------------------------------------------------------------
__global__ __launch_bounds__(128) void k_dyn(const float* __restrict__ ba) {
    int idx = blockIdx.x * 128 + threadIdx.x;   // (n,o,h,w)
    int w = idx & (WW-1);
    int h = (idx >> 7) & (HH-1);
    int o = (idx >> 14) & 1;
    int n = idx >> 15;

    float acc = ba[o];
    #pragma unroll
    for (int sp = 0; sp < NSPLIT; sp++) {
        #pragma unroll
        for (int i = 0; i < 3; i++) {
            int hh = h + i - 1;
            if (hh < 0 || hh >= HH) continue;
            #pragma unroll
            for (int j = 0; j < 3; j++) {
                int ww2 = w + j - 1;
                if (ww2 < 0 || ww2 >= WW) continue;
                acc += g_s4[((((sp*NB + n)*2 + o)*9 + (i*3 + j)) << 14) + hh*WW + ww2];
            }
        }
    }
    g_dyn[idx] = 1.f / (1.f + __expf(-acc));
}

// ---------------------------------------------------------------------------
// Tile geometry for window kernels: 64x8 px, 256 threads, warp = pixel row.
// ---------------------------------------------------------------------------
#define STW 64
#define STH 8
#define SHW (STW+4)   // 68
#define SHH (STH+4)   // 12

// div-free halo fill: warp covers rows {warp, warp+8}, lane covers float2 j,j+32
__device__ __forceinline__ void fill_tile(float st[GSIM][SHH][SHW],
                                          const float* gsrc, int nc_base,
                                          int h0, int w0, int warp, int lane) {
    #pragma unroll 4
    for (int c = 0; c < GSIM; c++) {
        const float* src = gsrc + ((nc_base + c) << 14);
        #pragma unroll
        for (int r2 = 0; r2 < 2; r2++) {
            int yy = warp + 8*r2;
            if (yy < SHH) {
                int gh = h0 + yy - 2;
                bool hv = (gh >= 0) && (gh < HH);
                #pragma unroll
                for (int jo = 0; jo < 2; jo++) {
                    int j = lane + 32*jo;
                    if (j < 34) {
                        int xx = 2*j;
                        int gw = w0 + xx - 2;
                        float2 v = make_float2(0.f, 0.f);
                        if (hv) {
                            if (gw >= 0 && gw + 1 < WW) {
                                v = *(const float2*)&src[gh*WW + gw];
                            } else {
                                if (gw >= 0 && gw < WW)         v.x = src[gh*WW + gw];
                                if (gw + 1 >= 0 && gw + 1 < WW) v.y = src[gh*WW + gw + 1];
                            }
                        }
                        *(float2*)&st[c][yy][xx] = v;
                    }
                }
            }
        }
    }
}

// ---------------------------------------------------------------------------
// Kernel 5: partial similarities, 16-ch group, dy-outer (10 live accumulators).
// ---------------------------------------------------------------------------
__global__ __launch_bounds__(256,4) void k_sim() {
    __shared__ __align__(16) float st[GSIM][SHH][SHW];   // 52.2 KB

    int lane = threadIdx.x & 31;
    int warp = threadIdx.x >> 5;
    int w0 = blockIdx.x * STW;
    int h0 = blockIdx.y * STH;
    int g  = blockIdx.z & (NGRP-1);
    int n  = blockIdx.z >> 3;
    int c0 = g * GSIM;
    int h  = h0 + warp;
    int wA = w0 + 2*lane;
    int pixA = h*WW + wA;

    fill_tile(st, g_key, n*CH + c0, h0, w0, warp, lane);

    // q resident in regs (16 independent LDG.64)
    float2 q2[GSIM];
    #pragma unroll
    for (int c = 0; c < GSIM; c++)
        q2[c] = *(const float2*)&g_qry[((n*CH + c0 + c) << 14) + pixA];

    __syncthreads();

    #pragma unroll
    for (int dy = 0; dy < 5; dy++) {
        float sA[5], sB[5];
        #pragma unroll
        for (int t = 0; t < 5; t++) { sA[t] = 0.f; sB[t] = 0.f; }

        #pragma unroll
        for (int c = 0; c < GSIM; c++) {
            float2 t0 = *(float2*)&st[c][warp+dy][2*lane + 0];
            float2 t1 = *(float2*)&st[c][warp+dy][2*lane + 2];
            float2 t2 = *(float2*)&st[c][warp+dy][2*lane + 4];
            sA[0] += q2[c].x * t0.x;
            sA[1] += q2[c].x * t0.y;
            sA[2] += q2[c].x * t1.x;
            sA[3] += q2[c].x * t1.y;
            sA[4] += q2[c].x * t2.x;
            sB[0] += q2[c].y * t0.y;
            sB[1] += q2[c].y * t1.x;
            sB[2] += q2[c].y * t1.y;
            sB[3] += q2[c].y * t2.x;
            sB[4] += q2[c].y * t2.y;
        }

        #pragma unroll
        for (int dx = 0; dx < 5; dx++) {
            float2 o; o.x = sA[dx]; o.y = sB[dx];
            *(float2*)&g_psim[(((n*NGRP + g)*25 + dy*5 + dx) << 14) + pixA] = o;
        }
    }
}

// ---------------------------------------------------------------------------
// Kernel 6: reduce 8 partials, softmax over 25 taps, fold gates. 2 px/thread.
// ---------------------------------------------------------------------------
__global__ __launch_bounds__(128) void k_smax() {
    int idx = blockIdx.x * 128 + threadIdx.x;     // covers 2 pixels
    int px  = idx * 2;
    int pix = px & (PLANE-1);
    int n   = px >> 14;

    float sA[25], sB[25];
    #pragma unroll
    for (int k = 0; k < 25; k++) { sA[k] = 0.f; sB[k] = 0.f; }
    #pragma unroll
    for (int g = 0; g < NGRP; g++)
        #pragma unroll
        for (int k = 0; k < 25; k++) {
            float2 v = *(const float2*)&g_psim[(((n*NGRP + g)*25 + k) << 14) + pix];
            sA[k] += v.x; sB[k] += v.y;
        }

    float mA = sA[0], mB = sB[0];
    #pragma unroll
    for (int k = 1; k < 25; k++) { mA = fmaxf(mA, sA[k]); mB = fmaxf(mB, sB[k]); }
    float suA = 0.f, suB = 0.f;
    #pragma unroll
    for (int k = 0; k < 25; k++) {
        sA[k] = __expf(sA[k] - mA); suA += sA[k];
        sB[k] = __expf(sB[k] - mB); suB += sB[k];
    }

    float2 d0 = *(const float2*)&g_dyn[((n*2 + 0) << 14) + pix];
    float2 d1 = *(const float2*)&g_dyn[((n*2 + 1) << 14) + pix];
    float scA = d0.x / suA;
    float scB = d0.y / suB;
    #pragma unroll
    for (int k = 0; k < 25; k++) {
        float2 o;
        o.x = sA[k] * scA;
        o.y = sB[k] * scB;
        if (k == 12) { o.x += d1.x; o.y += d1.y; }
        *(float2*)&g_w[((n*25 + k) << 14) + pix] = o;
    }
}

// ---------------------------------------------------------------------------
// Kernel 7: value aggregation, dy-outer (per-dy gate weights, 32 channel accums).
// ---------------------------------------------------------------------------
__global__ __launch_bounds__(256,4) void k_agg(float* __restrict__ out) {
    __shared__ __align__(16) float st[GSIM][SHH][SHW];   // 52.2 KB

    int lane = threadIdx.x & 31;
    int warp = threadIdx.x >> 5;
    int w0 = blockIdx.x * STW;
    int h0 = blockIdx.y * STH;
    int g  = blockIdx.z & (NGRP-1);
    int n  = blockIdx.z >> 3;
    int c0 = g * GSIM;
    int h  = h0 + warp;
    int wA = w0 + 2*lane;
    int pixA = h*WW + wA;

    fill_tile(st, g_val, n*CH + c0, h0, w0, warp, lane);

    float aA[GSIM], aB[GSIM];
    #pragma unroll
    for (int c = 0; c < GSIM; c++) { aA[c] = 0.f; aB[c] = 0.f; }

    __syncthreads();

    #pragma unroll
    for (int dy = 0; dy < 5; dy++) {
        float wgA[5], wgB[5];
        #pragma unroll
        for (int dx = 0; dx < 5; dx++) {
            float2 wv = *(const float2*)&g_w[((n*25 + dy*5 + dx) << 14) + pixA];
            wgA[dx] = wv.x; wgB[dx] = wv.y;
        }
        #pragma unroll
        for (int c = 0; c < GSIM; c++) {
            float2 t0 = *(float2*)&st[c][warp+dy][2*lane + 0];
            float2 t1 = *(float2*)&st[c][warp+dy][2*lane + 2];
            float2 t2 = *(float2*)&st[c][warp+dy][2*lane + 4];
            aA[c] += wgA[0]*t0.x + wgA[1]*t0.y + wgA[2]*t1.x + wgA[3]*t1.y + wgA[4]*t2.x;
            aB[c] += wgB[0]*t0.y + wgB[1]*t1.x + wgB[2]*t1.y + wgB[3]*t2.x + wgB[4]*t2.y;
        }
    }

    #pragma unroll
    for (int c = 0; c < GSIM; c++) {
        int gi = ((n*CH + c0 + c) << 14) + pixA;
        float2 lu = *(const float2*)&g_lrup[gi];
        float2 o; o.x = lu.x + aA[c]; o.y = lu.y + aB[c];
        *(float2*)&out[gi] = o;
    }
}

// ---------------------------------------------------------------------------
extern "C" void kernel_launch(void* const* d_in, const int* in_sizes, int n_in,
                              void* d_out, int out_size) {
    const float* hr = (const float*)d_in[0];
    const float* lr = (const float*)d_in[1];
    const float* wq = (const float*)d_in[2];
    const float* bq = (const float*)d_in[3];
    const float* wk = (const float*)d_in[4];
    const float* bk = (const float*)d_in[5];
    const float* wv = (const float*)d_in[6];
    const float* bv = (const float*)d_in[7];
    const float* wa = (const float*)d_in[8];
    const float* ba = (const float*)d_in[9];
    float* out = (float*)d_out;

    k_lrup<<<(NB*IMG)/256, 256>>>(lr);
    k_qkv <<<(NB*IMG/4)/128, 128>>>(hr, wq, bq, wk, bk, wv, bv);
    k_s   <<<dim3((NB*PLANE/2)/128, NSPLIT), 128>>>(wa);
    // k_sim stays 4th so the fixed ncu window lands on it
    k_sim <<<dim3(WW/STW, HH/STH, NB*NGRP), 256>>>();
    k_dyn <<<(NB*2*PLANE)/128, 128>>>(ba);
    k_smax<<<(NB*PLANE/2)/128, 128>>>();
    k_agg <<<dim3(WW/STW, HH/STH, NB*NGRP), 256>>>(out);
}